// round 1
// baseline (speedup 1.0000x reference)
#include <cuda_runtime.h>
#include <math.h>

// ---------------------------------------------------------------------------
// RecurrentGCN (GCLSTM, K=1 ChebConv -> edge data unused).
//   P[n, g*256+j] = x@W_g + h@Th_g + (bth_g + b_g)          (GEMM1, fused bias)
//   I,F = sigmoid(P + w_c* . c) ; T = tanh(P) ; C = F*c + I*T
//   O = sigmoid(P_o + w_co*C) ; H = O*tanh(C)
//   out = relu(H)@W_lin + b_lin                              (GEMM2, fused bias)
// Output tuple: [out | h0 | c0], each 50000*256 fp32.
// ---------------------------------------------------------------------------

#define NNODES 50000
#define HIDDIM 256
#define GATEN  1024   // 4 gates * 256

// Scratch (static device allocation — allowed; no cudaMalloc anywhere)
__device__ float g_P[(size_t)NNODES * GATEN];     // gate preactivations
__device__ float g_R[(size_t)NNODES * HIDDIM];    // relu(h0)
__device__ float g_W[512 * GATEN];                // packed [x-weights ; Th-weights]
__device__ float g_bias[GATEN];                   // bth_g + b_g packed

// ---------------------------------------------------------------------------
__global__ void pack_kernel(
    const float* __restrict__ Wi, const float* __restrict__ Wf,
    const float* __restrict__ Wc, const float* __restrict__ Wo,
    const float* __restrict__ Ti, const float* __restrict__ Tf,
    const float* __restrict__ Tc, const float* __restrict__ To,
    const float* __restrict__ bthi, const float* __restrict__ bthf,
    const float* __restrict__ bthc, const float* __restrict__ btho,
    const float* __restrict__ bi,  const float* __restrict__ bf,
    const float* __restrict__ bc,  const float* __restrict__ bo)
{
    int idx = blockIdx.x * blockDim.x + threadIdx.x;
    if (idx < GATEN) {
        int g = idx >> 8, jj = idx & 255;
        const float* bth = (g == 0) ? bthi : (g == 1) ? bthf : (g == 2) ? bthc : btho;
        const float* bb  = (g == 0) ? bi   : (g == 1) ? bf   : (g == 2) ? bc   : bo;
        g_bias[idx] = bth[jj] + bb[jj];
    }
    if (idx >= 512 * GATEN) return;
    int k = idx >> 10;          // 0..511
    int j = idx & 1023;         // 0..1023
    int g = j >> 8, jj = j & 255;
    float v;
    if (k < 256) {
        const float* W = (g == 0) ? Wi : (g == 1) ? Wf : (g == 2) ? Wc : Wo;
        v = W[k * 256 + jj];
    } else {
        const float* T = (g == 0) ? Ti : (g == 1) ? Tf : (g == 2) ? Tc : To;
        v = T[(k - 256) * 256 + jj];
    }
    g_W[idx] = v;
}

// ---------------------------------------------------------------------------
// SGEMM: C[M,N] = A1[M,256] @ B[0:256,N]  (+ A2[M,256] @ B[256:512,N] if Ktot==512)
// row-major everywhere; BM=BN=128, BK=8, 256 threads, 8x8 per thread,
// double-buffered shared memory, optional fused bias.
// ---------------------------------------------------------------------------
__global__ __launch_bounds__(256, 2)
void sgemm128(const float* __restrict__ A1, const float* __restrict__ A2,
              const float* __restrict__ B,
              float* __restrict__ C,
              int M, int N, int Ktot,
              const float* __restrict__ bias)
{
    const int BM = 128, BN = 128, BK = 8;
    __shared__ float As[2][BK][BM];
    __shared__ float Bs[2][BK][BN];

    const int tid  = threadIdx.x;
    const int m0   = blockIdx.y * BM;
    const int n0   = blockIdx.x * BN;

    const int a_row = tid >> 1;           // 0..127
    const int a_col = (tid & 1) << 2;     // 0 or 4
    const int b_row = tid >> 5;           // 0..7
    const int b_col = (tid & 31) << 2;    // 0..124

    const int tx = tid & 15;              // 0..15 -> col group
    const int ty = tid >> 4;              // 0..15 -> row group

    float acc[8][8];
#pragma unroll
    for (int i = 0; i < 8; ++i)
#pragma unroll
        for (int j = 0; j < 8; ++j) acc[i][j] = 0.f;

    float4 av, bv;

    auto fetch = [&](int kt) {
        const float* A = (kt < 256) ? A1 : A2;
        int kk  = (kt & 255) + a_col;
        int row = m0 + a_row;
        av = make_float4(0.f, 0.f, 0.f, 0.f);
        if (row < M)
            av = *reinterpret_cast<const float4*>(A + (size_t)row * 256 + kk);
        bv = *reinterpret_cast<const float4*>(B + (size_t)(kt + b_row) * N + n0 + b_col);
    };
    auto put = [&](int buf) {
        As[buf][a_col + 0][a_row] = av.x;
        As[buf][a_col + 1][a_row] = av.y;
        As[buf][a_col + 2][a_row] = av.z;
        As[buf][a_col + 3][a_row] = av.w;
        *reinterpret_cast<float4*>(&Bs[buf][b_row][b_col]) = bv;
    };

    fetch(0);
    put(0);
    __syncthreads();

    const int ntiles = Ktot >> 3;
    for (int t = 0; t < ntiles; ++t) {
        const int buf = t & 1;
        if (t + 1 < ntiles) fetch((t + 1) << 3);

#pragma unroll
        for (int k = 0; k < BK; ++k) {
            float a[8], b[8];
#pragma unroll
            for (int i = 0; i < 8; ++i) a[i] = As[buf][k][ty * 8 + i];
#pragma unroll
            for (int j = 0; j < 8; ++j) b[j] = Bs[buf][k][tx * 8 + j];
#pragma unroll
            for (int i = 0; i < 8; ++i)
#pragma unroll
                for (int j = 0; j < 8; ++j)
                    acc[i][j] = fmaf(a[i], b[j], acc[i][j]);
        }

        if (t + 1 < ntiles) put(buf ^ 1);
        __syncthreads();
    }

#pragma unroll
    for (int i = 0; i < 8; ++i) {
        int row = m0 + ty * 8 + i;
        if (row >= M) continue;
#pragma unroll
        for (int j = 0; j < 8; j += 4) {
            int col = n0 + tx * 8 + j;
            float4 v;
            v.x = acc[i][j + 0];
            v.y = acc[i][j + 1];
            v.z = acc[i][j + 2];
            v.w = acc[i][j + 3];
            if (bias) {
                v.x += bias[col];
                v.y += bias[col + 1];
                v.z += bias[col + 2];
                v.w += bias[col + 3];
            }
            *reinterpret_cast<float4*>(C + (size_t)row * N + col) = v;
        }
    }
}

// ---------------------------------------------------------------------------
__global__ void gates_kernel(const float* __restrict__ c_in,
                             const float* __restrict__ wci,
                             const float* __restrict__ wcf,
                             const float* __restrict__ wco,
                             float* __restrict__ h_out,
                             float* __restrict__ c_out)
{
    size_t idx = (size_t)blockIdx.x * blockDim.x + threadIdx.x;
    if (idx >= (size_t)NNODES * HIDDIM) return;
    size_t n = idx >> 8;
    int j = (int)(idx & 255);
    const float* P = g_P + n * GATEN;

    float cv = c_in[idx];
    float pi = P[j];
    float pf = P[256 + j];
    float pc = P[512 + j];
    float po = P[768 + j];

    float I = 1.f / (1.f + expf(-(pi + __ldg(&wci[j]) * cv)));
    float F = 1.f / (1.f + expf(-(pf + __ldg(&wcf[j]) * cv)));
    float T = tanhf(pc);
    float C = F * cv + I * T;
    float O = 1.f / (1.f + expf(-(po + __ldg(&wco[j]) * C)));
    float H = O * tanhf(C);

    h_out[idx] = H;
    c_out[idx] = C;
    g_R[idx]   = (H > 0.f) ? H : 0.f;
}

// ---------------------------------------------------------------------------
extern "C" void kernel_launch(void* const* d_in, const int* in_sizes, int n_in,
                              void* d_out, int out_size)
{
    const float* x    = (const float*)d_in[0];
    // d_in[1] edge_index (int32), d_in[2] edge_weight -> unused (K=1 ChebConv)
    const float* h    = (const float*)d_in[3];
    const float* c    = (const float*)d_in[4];
    const float* Wi   = (const float*)d_in[5];
    const float* Wf   = (const float*)d_in[6];
    const float* Wc   = (const float*)d_in[7];
    const float* Wo   = (const float*)d_in[8];
    const float* Ti   = (const float*)d_in[9];
    const float* Tf   = (const float*)d_in[10];
    const float* Tc   = (const float*)d_in[11];
    const float* To   = (const float*)d_in[12];
    const float* bthi = (const float*)d_in[13];
    const float* bthf = (const float*)d_in[14];
    const float* bthc = (const float*)d_in[15];
    const float* btho = (const float*)d_in[16];
    const float* wci  = (const float*)d_in[17];
    const float* wcf  = (const float*)d_in[18];
    const float* wco  = (const float*)d_in[19];
    const float* bi   = (const float*)d_in[20];
    const float* bf   = (const float*)d_in[21];
    const float* bc   = (const float*)d_in[22];
    const float* bo   = (const float*)d_in[23];
    const float* Wlin = (const float*)d_in[24];
    const float* blin = (const float*)d_in[25];
    float* out = (float*)d_out;

    float *pP, *pR, *pW, *pB;
    cudaGetSymbolAddress((void**)&pP, g_P);
    cudaGetSymbolAddress((void**)&pR, g_R);
    cudaGetSymbolAddress((void**)&pW, g_W);
    cudaGetSymbolAddress((void**)&pB, g_bias);

    // 1) pack weights + biases
    pack_kernel<<<(512 * GATEN + 255) / 256, 256>>>(
        Wi, Wf, Wc, Wo, Ti, Tf, Tc, To,
        bthi, bthf, bthc, btho, bi, bf, bc, bo);

    // 2) fused gate GEMM: P = x@W_all + h@Th_all + bias   (M=50000, N=1024, K=512)
    dim3 grid1(GATEN / 128, (NNODES + 127) / 128);
    sgemm128<<<grid1, 256>>>(x, h, pW, pP, NNODES, GATEN, 512, pB);

    // 3) elementwise gates -> h0, c0, relu scratch
    size_t elems = (size_t)NNODES * HIDDIM;
    gates_kernel<<<(unsigned)((elems + 255) / 256), 256>>>(
        c, wci, wcf, wco, out + elems, out + 2 * elems);

    // 4) out = relu(h0) @ W_lin + b_lin   (M=50000, N=256, K=256)
    dim3 grid2(HIDDIM / 128, (NNODES + 127) / 128);
    sgemm128<<<grid2, 256>>>(pR, nullptr, Wlin, out, NNODES, HIDDIM, 256, blin);
}

// round 3
// speedup vs baseline: 4.6180x; 4.6180x over previous
#include <cuda_runtime.h>
#include <cuda_fp16.h>
#include <stdint.h>
#include <math.h>

// ---------------------------------------------------------------------------
// GCLSTM (K=1 ChebConv -> edge data unused). HMMA (mma.sync) fp16 tensor path
// (tcgen05 unavailable: harness compiles at compute_103, not 103a).
//   GEMM1: P = [x|h](fp32->fp16 in-flight) @ Wt^T + bias  (M=50000,N=1024,K=512)
//   gates: h0, c0, R=relu(h0) fp16
//   GEMM2: out = R @ WlinT^T + b_lin                      (M=50000,N=256, K=256)
// Output tuple: [out | h0 | c0], each 50000*256 fp32.
// ---------------------------------------------------------------------------

#define NNODES 50000
#define GATEN  1024

__device__ float  g_P[(size_t)NNODES * GATEN];   // gate preactivations (fp32)
__device__ __half g_R[(size_t)NNODES * 256];     // relu(h0) fp16
__device__ __half g_Wt[1024 * 512];              // GEMM1 B: [n][k] = Wall[k][n]
__device__ __half g_WlT[256 * 256];              // GEMM2 B: [n][k] = Wlin[k][n]
__device__ float  g_bias[1024];                  // bth_g + b_g

// ---------------------------------------------------------------------------
__device__ __forceinline__ uint32_t smem_u32(const void* p) {
    uint32_t a;
    asm("{ .reg .u64 t; cvta.to.shared.u64 t, %1; cvt.u32.u64 %0, t; }"
        : "=r"(a) : "l"(p));
    return a;
}
__device__ __forceinline__ void ldmA4(uint32_t* a, uint32_t addr) {
    asm volatile("ldmatrix.sync.aligned.m8n8.x4.shared.b16 {%0,%1,%2,%3}, [%4];"
        : "=r"(a[0]), "=r"(a[1]), "=r"(a[2]), "=r"(a[3]) : "r"(addr));
}
__device__ __forceinline__ void ldmB2(uint32_t* b, uint32_t addr) {
    asm volatile("ldmatrix.sync.aligned.m8n8.x2.shared.b16 {%0,%1}, [%2];"
        : "=r"(b[0]), "=r"(b[1]) : "r"(addr));
}
__device__ __forceinline__ void mma16816(float* d, const uint32_t* a, const uint32_t* b) {
    asm volatile(
        "mma.sync.aligned.m16n8k16.row.col.f32.f16.f16.f32 "
        "{%0,%1,%2,%3},{%4,%5,%6,%7},{%8,%9},{%0,%1,%2,%3};"
        : "+f"(d[0]), "+f"(d[1]), "+f"(d[2]), "+f"(d[3])
        : "r"(a[0]), "r"(a[1]), "r"(a[2]), "r"(a[3]), "r"(b[0]), "r"(b[1]));
}

// ---------------------------------------------------------------------------
// HMMA GEMM: C[M,Ntot] = A @ B^T + bias.
//   A: (A16 != 0) ? fp16 [M,K]  :  fp32 [x | h] (two 256-col halves)
//   B: fp16 [Ntot, K] (K contiguous)
// Tiles: BM=128, BN=128, BK=32; 256 thr = 8 warps (2m x 4n), warp 64x32.
// ---------------------------------------------------------------------------
#define AS_STRIDE 40   // 32 halves + 8 pad (80 bytes/row)

__global__ void __launch_bounds__(256)
hmma_gemm(const float* __restrict__ Ax, const float* __restrict__ Ah,
          const __half* __restrict__ A16,
          const __half* __restrict__ B,
          float* __restrict__ C, const float* __restrict__ bias,
          int M, int Ntot, int K)
{
    __shared__ __align__(16) __half As[2][128][AS_STRIDE];
    __shared__ __align__(16) __half Bs[2][128][AS_STRIDE];
    __shared__ float sbias[128];

    const int tid  = threadIdx.x;
    const int lane = tid & 31;
    const int wid  = tid >> 5;
    const int warpm = wid >> 2;        // 0..1
    const int warpn = wid & 3;         // 0..3
    const int m0 = blockIdx.y * 128;
    const int n0 = blockIdx.x * 128;

    const uint32_t asb = smem_u32(&As[0][0][0]);
    const uint32_t bsb = smem_u32(&Bs[0][0][0]);
    const uint32_t BUFB = 128 * AS_STRIDE * 2;   // bytes per buffer

    for (int i = tid; i < 128; i += 256) sbias[i] = bias[n0 + i];

    float acc[4][4][4];
#pragma unroll
    for (int mt = 0; mt < 4; ++mt)
#pragma unroll
        for (int nt = 0; nt < 4; ++nt)
#pragma unroll
            for (int e = 0; e < 4; ++e) acc[mt][nt][e] = 0.f;

    const int nch = K >> 5;

    // register staging for prefetch
    uint32_t arg[8];   // A fp32 path: 4 float4 -> 8 u32 (halves)
    uint4    ar16[2];  // A fp16 path
    uint4    brg[2];   // B

    auto fetchA = [&](int kc) {
        if (A16) {
#pragma unroll
            for (int q = 0; q < 2; ++q) {
                int u = tid + q * 256;
                int r = u >> 2, kq = u & 3;
                int gr = m0 + r;
                ar16[q] = make_uint4(0, 0, 0, 0);
                if (gr < M)
                    ar16[q] = *(const uint4*)(A16 + (size_t)gr * K + kc * 32 + kq * 8);
            }
        } else {
            const float* src = (kc < 8) ? Ax : Ah;
            const int cb = (kc & 7) * 32;
#pragma unroll
            for (int q = 0; q < 4; ++q) {
                int u = tid + q * 256;
                int r = u >> 3, kq = u & 7;
                int gr = m0 + r;
                float4 f = make_float4(0.f, 0.f, 0.f, 0.f);
                if (gr < M)
                    f = *(const float4*)(src + (size_t)gr * 256 + cb + kq * 4);
                __half2 h0 = __floats2half2_rn(f.x, f.y);
                __half2 h1 = __floats2half2_rn(f.z, f.w);
                arg[q * 2 + 0] = *(uint32_t*)&h0;
                arg[q * 2 + 1] = *(uint32_t*)&h1;
            }
        }
    };
    auto fetchB = [&](int kc) {
#pragma unroll
        for (int q = 0; q < 2; ++q) {
            int u = tid + q * 256;
            int r = u >> 2, kq = u & 3;
            brg[q] = *(const uint4*)(B + (size_t)(n0 + r) * K + kc * 32 + kq * 8);
        }
    };
    auto storeA = [&](int buf) {
        if (A16) {
#pragma unroll
            for (int q = 0; q < 2; ++q) {
                int u = tid + q * 256;
                int r = u >> 2, kq = u & 3;
                *(uint4*)(&As[buf][r][kq * 8]) = ar16[q];
            }
        } else {
#pragma unroll
            for (int q = 0; q < 4; ++q) {
                int u = tid + q * 256;
                int r = u >> 3, kq = u & 7;
                uint2 v = make_uint2(arg[q * 2], arg[q * 2 + 1]);
                *(uint2*)(&As[buf][r][kq * 4]) = v;
            }
        }
    };
    auto storeB = [&](int buf) {
#pragma unroll
        for (int q = 0; q < 2; ++q) {
            int u = tid + q * 256;
            int r = u >> 2, kq = u & 3;
            *(uint4*)(&Bs[buf][r][kq * 8]) = brg[q];
        }
    };

    // prologue: chunk 0 -> buf 0
    fetchA(0); fetchB(0);
    storeA(0); storeB(0);
    __syncthreads();

    const int mrow = warpm * 64 + (lane & 15);
    const int nrow = warpn * 32 + (lane & 7);
    const int aksel = (lane >> 4) * 8;          // 0 or 8
    const int bksel = ((lane >> 3) & 1) * 8;    // 0 or 8

    for (int t = 0; t < nch; ++t) {
        const int buf = t & 1;
        const bool pf = (t + 1 < nch);
        if (pf) { fetchA(t + 1); fetchB(t + 1); }

        const uint32_t abase = asb + buf * BUFB + mrow * (AS_STRIDE * 2);
        const uint32_t bbase = bsb + buf * BUFB + nrow * (AS_STRIDE * 2);

#pragma unroll
        for (int ks = 0; ks < 2; ++ks) {
            const int k0 = ks * 16;
            uint32_t afr[4][4], bfr[4][2];
#pragma unroll
            for (int mt = 0; mt < 4; ++mt)
                ldmA4(afr[mt], abase + mt * 16 * (AS_STRIDE * 2) + (k0 + aksel) * 2);
#pragma unroll
            for (int nt = 0; nt < 4; ++nt)
                ldmB2(bfr[nt], bbase + nt * 8 * (AS_STRIDE * 2) + (k0 + bksel) * 2);
#pragma unroll
            for (int mt = 0; mt < 4; ++mt)
#pragma unroll
                for (int nt = 0; nt < 4; ++nt)
                    mma16816(acc[mt][nt], afr[mt], bfr[nt]);
        }

        if (pf) { storeA(buf ^ 1); storeB(buf ^ 1); }
        __syncthreads();
    }

    // epilogue
#pragma unroll
    for (int mt = 0; mt < 4; ++mt) {
        int r0 = m0 + warpm * 64 + mt * 16 + (lane >> 2);
        int r1 = r0 + 8;
#pragma unroll
        for (int nt = 0; nt < 4; ++nt) {
            int cl = warpn * 32 + nt * 8 + (lane & 3) * 2;  // local col
            int cg = n0 + cl;
            if (r0 < M) {
                float2 v;
                v.x = acc[mt][nt][0] + sbias[cl];
                v.y = acc[mt][nt][1] + sbias[cl + 1];
                *(float2*)(C + (size_t)r0 * Ntot + cg) = v;
            }
            if (r1 < M) {
                float2 v;
                v.x = acc[mt][nt][2] + sbias[cl];
                v.y = acc[mt][nt][3] + sbias[cl + 1];
                *(float2*)(C + (size_t)r1 * Ntot + cg) = v;
            }
        }
    }
}

// ---------------------------------------------------------------------------
__global__ void pack_kernel(
    const float* __restrict__ Wi, const float* __restrict__ Wf,
    const float* __restrict__ Wc, const float* __restrict__ Wo,
    const float* __restrict__ Ti, const float* __restrict__ Tf,
    const float* __restrict__ Tc, const float* __restrict__ To,
    const float* __restrict__ bthi, const float* __restrict__ bthf,
    const float* __restrict__ bthc, const float* __restrict__ btho,
    const float* __restrict__ bi, const float* __restrict__ bf,
    const float* __restrict__ bc, const float* __restrict__ bo,
    const float* __restrict__ Wlin)
{
    int idx = blockIdx.x * blockDim.x + threadIdx.x;
    if (idx < 524288) {                       // g_Wt[n][k] = Wall[k][n]
        int n = idx >> 9, k = idx & 511;
        int g = n >> 8, jj = n & 255;
        float v;
        if (k < 256) {
            const float* W = (g == 0) ? Wi : (g == 1) ? Wf : (g == 2) ? Wc : Wo;
            v = W[k * 256 + jj];
        } else {
            const float* T = (g == 0) ? Ti : (g == 1) ? Tf : (g == 2) ? Tc : To;
            v = T[(k - 256) * 256 + jj];
        }
        g_Wt[idx] = __float2half_rn(v);
    } else if (idx < 524288 + 65536) {        // g_WlT[n][k] = Wlin[k][n]
        int i2 = idx - 524288;
        int n = i2 >> 8, k = i2 & 255;
        g_WlT[i2] = __float2half_rn(Wlin[k * 256 + n]);
    } else if (idx < 524288 + 65536 + 1024) { // g_bias
        int j = idx - 524288 - 65536;
        int g = j >> 8, jj = j & 255;
        const float* bth = (g == 0) ? bthi : (g == 1) ? bthf : (g == 2) ? bthc : btho;
        const float* bb  = (g == 0) ? bi   : (g == 1) ? bf   : (g == 2) ? bc   : bo;
        g_bias[j] = bth[jj] + bb[jj];
    }
}

// ---------------------------------------------------------------------------
__device__ __forceinline__ float sigf(float x)  { return 1.f / (1.f + __expf(-x)); }
__device__ __forceinline__ float tanf_(float x) { return 2.f / (1.f + __expf(-2.f * x)) - 1.f; }

__global__ void gates_kernel(const float* __restrict__ c_in,
                             const float* __restrict__ wci,
                             const float* __restrict__ wcf,
                             const float* __restrict__ wco,
                             float* __restrict__ h_out,
                             float* __restrict__ c_out)
{
    int idx = blockIdx.x * blockDim.x + threadIdx.x;   // NNODES*64
    if (idx >= NNODES * 64) return;
    int n = idx >> 6;
    int j = (idx & 63) << 2;
    const float* P = g_P + (size_t)n * 1024;

    float4 pi = *(const float4*)(P + j);
    float4 pf = *(const float4*)(P + 256 + j);
    float4 pc = *(const float4*)(P + 512 + j);
    float4 po = *(const float4*)(P + 768 + j);
    float4 cv = *(const float4*)(c_in + (size_t)n * 256 + j);
    float4 wi = *(const float4*)(wci + j);
    float4 wf = *(const float4*)(wcf + j);
    float4 wo = *(const float4*)(wco + j);

    float4 H, Cn;
    {
        float I = sigf(pi.x + wi.x * cv.x), F = sigf(pf.x + wf.x * cv.x);
        Cn.x = F * cv.x + I * tanf_(pc.x);
        H.x = sigf(po.x + wo.x * Cn.x) * tanf_(Cn.x);
    }
    {
        float I = sigf(pi.y + wi.y * cv.y), F = sigf(pf.y + wf.y * cv.y);
        Cn.y = F * cv.y + I * tanf_(pc.y);
        H.y = sigf(po.y + wo.y * Cn.y) * tanf_(Cn.y);
    }
    {
        float I = sigf(pi.z + wi.z * cv.z), F = sigf(pf.z + wf.z * cv.z);
        Cn.z = F * cv.z + I * tanf_(pc.z);
        H.z = sigf(po.z + wo.z * Cn.z) * tanf_(Cn.z);
    }
    {
        float I = sigf(pi.w + wi.w * cv.w), F = sigf(pf.w + wf.w * cv.w);
        Cn.w = F * cv.w + I * tanf_(pc.w);
        H.w = sigf(po.w + wo.w * Cn.w) * tanf_(Cn.w);
    }

    size_t off = (size_t)n * 256 + j;
    *(float4*)(h_out + off) = H;
    *(float4*)(c_out + off) = Cn;

    __half2 r01 = __floats2half2_rn(fmaxf(H.x, 0.f), fmaxf(H.y, 0.f));
    __half2 r23 = __floats2half2_rn(fmaxf(H.z, 0.f), fmaxf(H.w, 0.f));
    uint2 rv;
    rv.x = *(uint32_t*)&r01;
    rv.y = *(uint32_t*)&r23;
    *(uint2*)(g_R + off) = rv;
}

// ---------------------------------------------------------------------------
extern "C" void kernel_launch(void* const* d_in, const int* in_sizes, int n_in,
                              void* d_out, int out_size)
{
    const float* x    = (const float*)d_in[0];
    // d_in[1] edge_index, d_in[2] edge_weight -> unused (K=1 ChebConv)
    const float* h    = (const float*)d_in[3];
    const float* c    = (const float*)d_in[4];
    const float* Wi   = (const float*)d_in[5];
    const float* Wf   = (const float*)d_in[6];
    const float* Wc   = (const float*)d_in[7];
    const float* Wo   = (const float*)d_in[8];
    const float* Ti   = (const float*)d_in[9];
    const float* Tf   = (const float*)d_in[10];
    const float* Tc   = (const float*)d_in[11];
    const float* To   = (const float*)d_in[12];
    const float* bthi = (const float*)d_in[13];
    const float* bthf = (const float*)d_in[14];
    const float* bthc = (const float*)d_in[15];
    const float* btho = (const float*)d_in[16];
    const float* wci  = (const float*)d_in[17];
    const float* wcf  = (const float*)d_in[18];
    const float* wco  = (const float*)d_in[19];
    const float* bi   = (const float*)d_in[20];
    const float* bf   = (const float*)d_in[21];
    const float* bc   = (const float*)d_in[22];
    const float* bo   = (const float*)d_in[23];
    const float* Wlin = (const float*)d_in[24];
    const float* blin = (const float*)d_in[25];
    float* out = (float*)d_out;

    float *pP, *pBias;
    __half *pWt, *pWlT, *pR;
    cudaGetSymbolAddress((void**)&pP, g_P);
    cudaGetSymbolAddress((void**)&pBias, g_bias);
    cudaGetSymbolAddress((void**)&pWt, g_Wt);
    cudaGetSymbolAddress((void**)&pWlT, g_WlT);
    cudaGetSymbolAddress((void**)&pR, g_R);

    // 1) pack weights/bias to fp16
    pack_kernel<<<(524288 + 65536 + 1024 + 255) / 256, 256>>>(
        Wi, Wf, Wc, Wo, Ti, Tf, Tc, To,
        bthi, bthf, bthc, btho, bi, bf, bc, bo, Wlin);

    // 2) GEMM1: P = [x|h] @ Wt^T + bias   (M=50000, N=1024, K=512)
    hmma_gemm<<<dim3(8, (NNODES + 127) / 128), 256>>>(
        x, h, nullptr, pWt, pP, pBias, NNODES, GATEN, 512);

    // 3) gates -> h0, c0, R
    const size_t elems = (size_t)NNODES * 256;
    gates_kernel<<<(NNODES * 64 + 255) / 256, 256>>>(
        c, wci, wcf, wco, out + elems, out + 2 * elems);

    // 4) GEMM2: out = R @ WlinT^T + b_lin   (M=50000, N=256, K=256)
    hmma_gemm<<<dim3(2, (NNODES + 127) / 128), 256>>>(
        nullptr, nullptr, pR, pWlT, out, blin, NNODES, 256, 256);
}